// round 11
// baseline (speedup 1.0000x reference)
#include <cuda_runtime.h>
#include <cstdint>

#define THW 1024
#define DM  512
#define NH  8
#define DH  64
#define BS  4
#define TR  (BS*THW)       // 4096
#define LNEPS 1e-5f

// within-8-group permutation making MMA frag word pairs (t4, t4+4) adjacent
__host__ __device__ __forceinline__ int perm3(int r) { return (r < 4) ? 2 * r : 2 * r - 7; }

// ---------------- scratch ----------------
__device__ uint32_t g_xnh[(size_t)TR * 256];       // LN out fp16x2, pair-permuted words
__device__ uint32_t g_qk [(size_t)TR * 512];       // fp16x2 Q|K: [row][h*64 + (k?32:0) + word]
__device__ uint32_t g_oh [(size_t)TR * 256];       // attn out fp16x2, pair-permuted words
__device__ uint32_t g_wbh[1536 * 256];             // QKV B fp16x2 [n][word]
__device__ uint32_t g_wph[512 * 256];              // wp fp16x2 [n][word]
__device__ uint32_t g_vt [(size_t)32 * 64 * 512];  // bf16x2 V^T [z][e][cp], cp-pair-permuted
__device__ uint32_t g_mb [1024 * 32];              // M bit-packed

// ---------------- helpers ----------------
__device__ __forceinline__ uint32_t pack_bf16(float lo, float hi) {
    uint32_t r;
    asm("cvt.rn.bf16x2.f32 %0, %1, %2;" : "=r"(r) : "f"(hi), "f"(lo));
    return r;
}
__device__ __forceinline__ uint32_t pack_f16(float lo, float hi) {
    uint32_t r;
    asm("cvt.rn.f16x2.f32 %0, %1, %2;" : "=r"(r) : "f"(hi), "f"(lo));
    return r;
}
__device__ __forceinline__ uint32_t smem_u32(const void* p) {
    uint32_t a;
    asm("{ .reg .u64 t; cvta.to.shared.u64 t, %1; cvt.u32.u64 %0, t; }" : "=r"(a) : "l"(p));
    return a;
}
__device__ __forceinline__ void cp16(uint32_t dst, const void* src) {
    asm volatile("cp.async.cg.shared.global [%0], [%1], 16;" :: "r"(dst), "l"(src));
}
__device__ __forceinline__ void cp_commit() { asm volatile("cp.async.commit_group;"); }

__device__ __forceinline__ void mma_f16(float d[4], const uint32_t a[4], uint32_t b0, uint32_t b1) {
    asm volatile(
        "mma.sync.aligned.m16n8k16.row.col.f32.f16.f16.f32 "
        "{%0,%1,%2,%3}, {%4,%5,%6,%7}, {%8,%9}, {%0,%1,%2,%3};"
        : "+f"(d[0]), "+f"(d[1]), "+f"(d[2]), "+f"(d[3])
        : "r"(a[0]), "r"(a[1]), "r"(a[2]), "r"(a[3]), "r"(b0), "r"(b1));
}
__device__ __forceinline__ void mma_bf16(float d[4], const uint32_t a[4], uint32_t b0, uint32_t b1) {
    asm volatile(
        "mma.sync.aligned.m16n8k16.row.col.f32.bf16.bf16.f32 "
        "{%0,%1,%2,%3}, {%4,%5,%6,%7}, {%8,%9}, {%0,%1,%2,%3};"
        : "+f"(d[0]), "+f"(d[1]), "+f"(d[2]), "+f"(d[3])
        : "r"(a[0]), "r"(a[1]), "r"(a[2]), "r"(a[3]), "r"(b0), "r"(b1));
}

// ---------------- LayerNorm -> fp16x2 pair-permuted words ----------------
__global__ void ln_kernel(const float* __restrict__ x,
                          const float* __restrict__ gamma,
                          const float* __restrict__ beta) {
    int row = blockIdx.x;
    int t = threadIdx.x;
    float2 v = ((const float2*)(x + (size_t)row * DM))[t];

    __shared__ float red[8];
    float s = v.x + v.y;
    #pragma unroll
    for (int o = 16; o; o >>= 1) s += __shfl_xor_sync(0xffffffffu, s, o);
    if ((t & 31) == 0) red[t >> 5] = s;
    __syncthreads();
    if (t < 8) {
        float m = red[t];
        #pragma unroll
        for (int o = 4; o; o >>= 1) m += __shfl_xor_sync(0xffu, m, o);
        if (t == 0) red[0] = m;
    }
    __syncthreads();
    float mu = red[0] * (1.0f / DM);
    __syncthreads();

    float d0 = v.x - mu, d1 = v.y - mu;
    float s2 = d0 * d0 + d1 * d1;
    #pragma unroll
    for (int o = 16; o; o >>= 1) s2 += __shfl_xor_sync(0xffffffffu, s2, o);
    if ((t & 31) == 0) red[t >> 5] = s2;
    __syncthreads();
    if (t < 8) {
        float m = red[t];
        #pragma unroll
        for (int o = 4; o; o >>= 1) m += __shfl_xor_sync(0xffu, m, o);
        if (t == 0) red[0] = m;
    }
    __syncthreads();
    float rstd = rsqrtf(red[0] * (1.0f / DM) + LNEPS);

    float2 gm = ((const float2*)gamma)[t];
    float2 bt = ((const float2*)beta)[t];
    float n0 = d0 * rstd * gm.x + bt.x;
    float n1 = d1 * rstd * gm.y + bt.y;
    int wp = (t & ~7) | perm3(t & 7);
    g_xnh[(size_t)row * 256 + wp] = pack_f16(n0, n1);
}

// ---------------- prep: weights -> fp16x2 pair-permuted; mask bitpack (merged) ----------------
__global__ void prep_all(const float* __restrict__ wq, const float* __restrict__ wk,
                         const float* __restrict__ wv, const float* __restrict__ wp,
                         const int* __restrict__ M) {
    int bid = blockIdx.x;
    if (bid < 2048) {
        size_t idx = (size_t)bid * 256 + threadIdx.x;
        if (idx < (size_t)1536 * 256) {
            int n = (int)(idx >> 8), u = (int)(idx & 255);
            int sel = n >> 9;
            int he = n & 511;
            int h = he >> 6, e = he & 63;
            const float* w = sel == 0 ? wq : sel == 1 ? wk : wv;
            float v0 = w[((size_t)h * 512 + 2 * u) * 64 + e];
            float v1 = w[((size_t)h * 512 + 2 * u + 1) * 64 + e];
            int wpp = (u & ~7) | perm3(u & 7);
            g_wbh[(size_t)n * 256 + wpp] = pack_f16(v0, v1);
        } else {
            size_t i2 = idx - (size_t)1536 * 256;
            int n = (int)(i2 >> 8), u = (int)(i2 & 255);
            float v0 = wp[(size_t)n * 512 + 2 * u];
            float v1 = wp[(size_t)n * 512 + 2 * u + 1];
            int wpp = (u & ~7) | perm3(u & 7);
            g_wph[(size_t)n * 256 + wpp] = pack_f16(v0, v1);
        }
    } else {
        int idx = (bid - 2048) * 256 + threadIdx.x;
        bool m = M[idx] != 0;
        uint32_t w = __ballot_sync(0xffffffffu, m);
        if ((idx & 31) == 0) g_mb[idx >> 5] = w;
    }
}

// ---------------- fp16 MMA GEMM, 3-stage cp.async, 1 barrier/iter ----------------
#define PKW 24
template <int NSUB>
__global__ __launch_bounds__(256) void gemm_h(const uint32_t* __restrict__ A,
                                              const uint32_t* __restrict__ Bw,
                                              float* __restrict__ C,
                                              const float* __restrict__ res,
                                              uint32_t* __restrict__ qk,
                                              uint32_t* __restrict__ vt,
                                              int ldc) {
    constexpr int NBLK = NSUB * 32;
    constexpr int GSTG = (128 + NBLK) * PKW;   // uint32 words per stage
    extern __shared__ uint32_t gsmh[];
    int tid = threadIdx.x, lane = tid & 31, warp = tid >> 5;
    int wm = (warp >> 2) * 64;
    int wn = (warp & 3) * NSUB * 8;
    int m0 = blockIdx.x * 128, n0 = blockIdx.y * NBLK;
    int g = lane >> 2, t4 = lane & 3;

    float acc[4][NSUB][4] = {};

    auto fill = [&](int kt, int s) {
        uint32_t ab = smem_u32(gsmh + s * GSTG);
        uint32_t bb = ab + 128 * PKW * 4;
        #pragma unroll
        for (int i = 0; i < 2; i++) {
            int c = tid + i * 256;
            int r = c >> 2, cc = c & 3;
            cp16(ab + (uint32_t)(r * PKW + cc * 4) * 4,
                 A + (size_t)(m0 + r) * 256 + kt * 16 + cc * 4);
        }
        #pragma unroll
        for (int i = 0; i < NSUB / 2; i++) {
            int c = tid + i * 256;
            int r = c >> 2, cc = c & 3;
            cp16(bb + (uint32_t)(r * PKW + cc * 4) * 4,
                 Bw + (size_t)(n0 + r) * 256 + kt * 16 + cc * 4);
        }
        cp_commit();
    };

    fill(0, 0);
    fill(1, 1);
    for (int kt = 0; kt < 16; kt++) {
        int st = kt % 3;
        if (kt < 15) asm volatile("cp.async.wait_group 1;" ::: "memory");
        else         asm volatile("cp.async.wait_group 0;" ::: "memory");
        __syncthreads();
        if (kt + 2 < 16) fill(kt + 2, (kt + 2) % 3);

        const uint32_t* As = gsmh + st * GSTG;
        const uint32_t* Bs = As + 128 * PKW;
        #pragma unroll
        for (int kb = 0; kb < 2; kb++) {
            uint32_t a[4][4], b[NSUB][2];
            #pragma unroll
            for (int mt = 0; mt < 4; mt++) {
                int r = wm + mt * 16 + g;
                uint2 f0 = *(const uint2*)(As + r * PKW + kb * 8 + 2 * t4);
                uint2 f1 = *(const uint2*)(As + (r + 8) * PKW + kb * 8 + 2 * t4);
                a[mt][0] = f0.x;
                a[mt][1] = f1.x;
                a[mt][2] = f0.y;
                a[mt][3] = f1.y;
            }
            #pragma unroll
            for (int nt = 0; nt < NSUB; nt++) {
                int n = wn + nt * 8 + g;
                uint2 bv = *(const uint2*)(Bs + n * PKW + kb * 8 + 2 * t4);
                b[nt][0] = bv.x;
                b[nt][1] = bv.y;
            }
            #pragma unroll
            for (int mt = 0; mt < 4; mt++)
                #pragma unroll
                for (int nt = 0; nt < NSUB; nt++)
                    mma_f16(acc[mt][nt], a[mt], b[nt][0], b[nt][1]);
        }
    }

    if (qk) {
        if (n0 >= 1024) {
            // ---- V: pack bf16 token-pairs transposed into g_vt (cp-pair perm) ----
            bool geven = (g & 1) == 0;
            #pragma unroll
            for (int mt = 0; mt < 4; mt++) {
                int ra = m0 + wm + mt * 16 + g;
                int b_ = ra >> 10, c_ = ra & 1023;
                #pragma unroll
                for (int nt = 0; nt < NSUB; nt++) {
                    int np = n0 - 1024 + wn + nt * 8 + t4 * 2;
                    int h_ = np >> 6, e0 = np & 63;
                    int z_ = h_ * 4 + b_;
                    float v0 = acc[mt][nt][0], v1 = acc[mt][nt][1];
                    float v2 = acc[mt][nt][2], v3 = acc[mt][nt][3];
                    float e0x = __shfl_xor_sync(0xffffffffu, v0, 4);
                    float e1x = __shfl_xor_sync(0xffffffffu, v1, 4);
                    float e2x = __shfl_xor_sync(0xffffffffu, v2, 4);
                    float e3x = __shfl_xor_sync(0xffffffffu, v3, 4);
                    size_t ebase = ((size_t)z_ * 64 + e0) * 512;
                    if (geven) {
                        int cp = c_ >> 1;
                        int cps = (cp & ~7) | perm3(cp & 7);
                        vt[ebase + cps]       = pack_bf16(v0, e0x);
                        vt[ebase + 512 + cps] = pack_bf16(v1, e1x);
                    } else {
                        int cp = (c_ + 7) >> 1;
                        int cps = (cp & ~7) | perm3(cp & 7);
                        vt[ebase + cps]       = pack_bf16(e2x, v2);
                        vt[ebase + 512 + cps] = pack_bf16(e3x, v3);
                    }
                }
            }
        } else {
            // ---- Q/K: pack fp16 e-pairs (pair-permuted) into g_qk ----
            #pragma unroll
            for (int mt = 0; mt < 4; mt++) {
                int r = m0 + wm + mt * 16 + g;
                #pragma unroll
                for (int nt = 0; nt < NSUB; nt++) {
                    int c = n0 + wn + nt * 8 + t4 * 2;
                    int isK = c >= 512;
                    int cl = c & 511;
                    int h_ = cl >> 6, e = cl & 63;
                    int p = e >> 1;
                    int word = h_ * 64 + isK * 32 + ((p & ~7) | perm3(p & 7));
                    qk[(size_t)r * 512 + word] =
                        pack_f16(acc[mt][nt][0], acc[mt][nt][1]);
                    qk[(size_t)(r + 8) * 512 + word] =
                        pack_f16(acc[mt][nt][2], acc[mt][nt][3]);
                }
            }
        }
        return;
    }

    #pragma unroll
    for (int mt = 0; mt < 4; mt++) {
        #pragma unroll
        for (int nt = 0; nt < NSUB; nt++) {
            int r = m0 + wm + mt * 16 + g;
            int c = n0 + wn + nt * 8 + t4 * 2;
            float v0 = acc[mt][nt][0], v1 = acc[mt][nt][1];
            float v2 = acc[mt][nt][2], v3 = acc[mt][nt][3];
            size_t o0 = (size_t)r * ldc + c;
            size_t o1 = (size_t)(r + 8) * ldc + c;
            if (res) {
                float2 r0 = *(const float2*)(res + o0);
                float2 r1 = *(const float2*)(res + o1);
                v0 += r0.x; v1 += r0.y; v2 += r1.x; v3 += r1.y;
            }
            *(float2*)(C + o0) = make_float2(v0, v1);
            *(float2*)(C + o1) = make_float2(v2, v3);
        }
    }
}

// ---------------- fused flash attention: fp16 QK^T, bf16 PV, bitmask, 2-stage ----------------
#define KW   40
#define FSTG_W (64 * KW * 2)
#define FSTG_B (FSTG_W * 4)                      // 20480 bytes per stage
__global__ __launch_bounds__(256, 2) void flash_kernel(const float* __restrict__ Bb) {
    extern __shared__ uint32_t smu[];
    int z = blockIdx.z;
    int h = z >> 2, b = z & 3;
    int q0 = blockIdx.x * 128;
    int tid = threadIdx.x, lane = tid & 31, warp = tid >> 5;
    int g = lane >> 2, t4 = lane & 3;

    size_t rowbase = (size_t)b * THW;
    uint32_t smbase = smem_u32(smu);

    uint32_t qa[4][4];
    {
        const uint32_t* Q0 = g_qk + (rowbase + q0 + warp * 16 + g) * 512 + h * 64;
        const uint32_t* Q1 = Q0 + 8 * 512;
        #pragma unroll
        for (int kb = 0; kb < 4; kb++) {
            uint2 f0 = *(const uint2*)(Q0 + kb * 8 + 2 * t4);
            uint2 f1 = *(const uint2*)(Q1 + kb * 8 + 2 * t4);
            qa[kb][0] = f0.x;
            qa[kb][1] = f1.x;
            qa[kb][2] = f0.y;
            qa[kb][3] = f1.y;
        }
    }

    float oacc[8][4] = {};
    float rs0 = 0.f, rs1 = 0.f;
    const float* Bz = Bb + (size_t)z * THW * THW;
    int qr0 = q0 + warp * 16 + g;
    int qr1 = qr0 + 8;
    const uint32_t* mrow0 = g_mb + (size_t)qr0 * 32;
    const uint32_t* mrow1 = g_mb + (size_t)qr1 * 32;

    auto fill = [&](int it, int s) {
        int c0 = it * 64;
        uint32_t kb_ = smbase + s * FSTG_B;
        uint32_t vb_ = kb_ + 64 * KW * 4;
        #pragma unroll
        for (int i = 0; i < 2; i++) {
            int c = tid + i * 256;
            int r = c >> 3, cc = c & 7;
            cp16(kb_ + (uint32_t)(r * KW + cc * 4) * 4,
                 g_qk + (rowbase + c0 + r) * 512 + h * 64 + 32 + cc * 4);
        }
        #pragma unroll
        for (int i = 0; i < 2; i++) {
            int c = tid + i * 256;
            int e = c >> 3, jj = c & 7;
            cp16(vb_ + (uint32_t)(e * KW + jj * 4) * 4,
                 &g_vt[((size_t)(z * 64) + e) * 512 + (c0 >> 1) + jj * 4]);
        }
        cp_commit();
    };

    fill(0, 0);
    for (int it = 0; it < 16; it++) {
        int st = it & 1;
        int c0 = it * 64;

        uint2 mw0 = *(const uint2*)(mrow0 + (c0 >> 5));
        uint2 mw1 = *(const uint2*)(mrow1 + (c0 >> 5));
        size_t bo0 = (size_t)qr0 * THW + c0 + 2 * t4;
        size_t bo1 = (size_t)qr1 * THW + c0 + 2 * t4;
        float2 nbA0 = *(const float2*)(Bz + bo0);
        float2 nbA1 = *(const float2*)(Bz + bo1);
        float2 nbB0 = *(const float2*)(Bz + bo0 + 8);
        float2 nbB1 = *(const float2*)(Bz + bo1 + 8);

        if (it < 15) {
            fill(it + 1, st ^ 1);
            asm volatile("cp.async.wait_group 1;" ::: "memory");
        } else {
            asm volatile("cp.async.wait_group 0;" ::: "memory");
        }
        __syncthreads();
        const uint32_t* Ks = smu + st * FSTG_W;
        const uint32_t* Vst = Ks + 64 * KW;

        #pragma unroll
        for (int j = 0; j < 4; j++) {
            float2 bA0 = nbA0, bA1 = nbA1, bB0 = nbB0, bB1 = nbB1;
            if (j < 3) {
                size_t po = (j + 1) * 16;
                nbA0 = *(const float2*)(Bz + bo0 + po);
                nbA1 = *(const float2*)(Bz + bo1 + po);
                nbB0 = *(const float2*)(Bz + bo0 + po + 8);
                nbB1 = *(const float2*)(Bz + bo1 + po + 8);
            }

            float saccA[4] = {}, saccB[4] = {};
            const uint32_t* krA = Ks + (j * 16 + g) * KW;
            const uint32_t* krB = krA + 8 * KW;
            #pragma unroll
            for (int kb = 0; kb < 4; kb++) {
                uint2 fa = *(const uint2*)(krA + kb * 8 + 2 * t4);
                uint2 fb = *(const uint2*)(krB + kb * 8 + 2 * t4);
                mma_f16(saccA, qa[kb], fa.x, fa.y);
                mma_f16(saccB, qa[kb], fb.x, fb.y);
            }

            uint32_t w0 = (j & 2) ? mw0.y : mw0.x;
            uint32_t w1 = (j & 2) ? mw1.y : mw1.x;
            int sh = (j & 1) * 16 + 2 * t4;
            uint32_t a0m = (w0 >> sh) & 1u,       a1m = (w0 >> (sh + 1)) & 1u;
            uint32_t b0m = (w0 >> (sh + 8)) & 1u, b1m = (w0 >> (sh + 9)) & 1u;
            uint32_t c0m = (w1 >> sh) & 1u,       c1m = (w1 >> (sh + 1)) & 1u;
            uint32_t d0m = (w1 >> (sh + 8)) & 1u, d1m = (w1 >> (sh + 9)) & 1u;

            float pA0 = a0m ? 0.f : __expf(fmaf(saccA[0], 0.125f, bA0.x));
            float pA1 = a1m ? 0.f : __expf(fmaf(saccA[1], 0.125f, bA0.y));
            float pA2 = c0m ? 0.f : __expf(fmaf(saccA[2], 0.125f, bA1.x));
            float pA3 = c1m ? 0.f : __expf(fmaf(saccA[3], 0.125f, bA1.y));
            float pB0 = b0m ? 0.f : __expf(fmaf(saccB[0], 0.125f, bB0.x));
            float pB1 = b1m ? 0.f : __expf(fmaf(saccB[1], 0.125f, bB0.y));
            float pB2 = d0m ? 0.f : __expf(fmaf(saccB[2], 0.125f, bB1.x));
            float pB3 = d1m ? 0.f : __expf(fmaf(saccB[3], 0.125f, bB1.y));
            rs0 += pA0 + pA1 + pB0 + pB1;
            rs1 += pA2 + pA3 + pB2 + pB3;

            uint32_t pa[4];
            pa[0] = pack_bf16(pA0, pA1);
            pa[1] = pack_bf16(pA2, pA3);
            pa[2] = pack_bf16(pB0, pB1);
            pa[3] = pack_bf16(pB2, pB3);

            #pragma unroll
            for (int ne = 0; ne < 8; ne++) {
                uint2 bv = *(const uint2*)(Vst + (ne * 8 + g) * KW + j * 8 + 2 * t4);
                mma_bf16(oacc[ne], pa, bv.x, bv.y);
            }
        }
        __syncthreads();
    }

    rs0 += __shfl_xor_sync(0xffffffffu, rs0, 1);
    rs0 += __shfl_xor_sync(0xffffffffu, rs0, 2);
    rs1 += __shfl_xor_sync(0xffffffffu, rs1, 1);
    rs1 += __shfl_xor_sync(0xffffffffu, rs1, 2);
    float inv0 = 1.0f / rs0, inv1 = 1.0f / rs1;

    // store O as fp16x2 pair-permuted words (A operand of proj GEMM)
    size_t orow0 = (rowbase + qr0) * (size_t)256;
    size_t orow1 = (rowbase + qr1) * (size_t)256;
    #pragma unroll
    for (int nt = 0; nt < 8; nt++) {
        int wi = h * 32 + nt * 4 + t4;
        int wpp = (wi & ~7) | perm3(wi & 7);
        g_oh[orow0 + wpp] = pack_f16(oacc[nt][0] * inv0, oacc[nt][1] * inv0);
        g_oh[orow1 + wpp] = pack_f16(oacc[nt][2] * inv1, oacc[nt][3] * inv1);
    }
}

// ---------------- launch ----------------
extern "C" void kernel_launch(void* const* d_in, const int* in_sizes, int n_in,
                              void* d_out, int out_size) {
    const float* x     = (const float*)d_in[0];
    const float* Bb    = (const float*)d_in[1];
    const int*   Mm    = (const int*)  d_in[2];
    const float* gamma = (const float*)d_in[3];
    const float* beta  = (const float*)d_in[4];
    const float* wq    = (const float*)d_in[5];
    const float* wk    = (const float*)d_in[6];
    const float* wv    = (const float*)d_in[7];
    const float* wp    = (const float*)d_in[8];
    float* out = (float*)d_out;

    void *p_xnh, *p_oh, *p_wbh, *p_wph, *p_vt, *p_qk;
    cudaGetSymbolAddress(&p_xnh, g_xnh);
    cudaGetSymbolAddress(&p_oh,  g_oh);
    cudaGetSymbolAddress(&p_wbh, g_wbh);
    cudaGetSymbolAddress(&p_wph, g_wph);
    cudaGetSymbolAddress(&p_vt,  g_vt);
    cudaGetSymbolAddress(&p_qk,  g_qk);

    const int gemm4_smem = (128 + 128) * PKW * 3 * 4;  // 73728
    const int gemm2_smem = (128 + 64)  * PKW * 3 * 4;  // 55296
    const int flash_smem = FSTG_B * 2;                 // 40960
    cudaFuncSetAttribute(gemm_h<4>,    cudaFuncAttributeMaxDynamicSharedMemorySize, gemm4_smem);
    cudaFuncSetAttribute(gemm_h<2>,    cudaFuncAttributeMaxDynamicSharedMemorySize, gemm2_smem);
    cudaFuncSetAttribute(flash_kernel, cudaFuncAttributeMaxDynamicSharedMemorySize, flash_smem);

    ln_kernel<<<TR, 256>>>(x, gamma, beta);
    prep_all<<<2048 + 4096, 256>>>(wq, wk, wv, wp, Mm);
    gemm_h<4><<<dim3(TR / 128, 1536 / 128), 256, gemm4_smem>>>(
        (const uint32_t*)p_xnh, (const uint32_t*)p_wbh, nullptr, nullptr,
        (uint32_t*)p_qk, (uint32_t*)p_vt, 1536);
    flash_kernel<<<dim3(THW / 128, 1, NH * BS), 256, flash_smem>>>(Bb);
    gemm_h<2><<<dim3(TR / 128, DM / 64), 256, gemm2_smem>>>(
        (const uint32_t*)p_oh, (const uint32_t*)p_wph, out, x,
        nullptr, nullptr, DM);
}

// round 12
// speedup vs baseline: 1.5209x; 1.5209x over previous
#include <cuda_runtime.h>
#include <cstdint>

#define THW 1024
#define DM  512
#define NH  8
#define DH  64
#define BS  4
#define TR  (BS*THW)       // 4096
#define LNEPS 1e-5f

// within-8-group permutation making MMA frag word pairs (t4, t4+4) adjacent
__host__ __device__ __forceinline__ int perm3(int r) { return (r < 4) ? 2 * r : 2 * r - 7; }

// ---------------- scratch ----------------
__device__ uint32_t g_xnh[(size_t)TR * 256];       // LN out fp16x2, pair-permuted words
__device__ uint32_t g_qk [(size_t)TR * 512];       // fp16x2 Q|K: [row][h*64 + (k?32:0) + word]
__device__ uint32_t g_oh [(size_t)TR * 256];       // attn out fp16x2, pair-permuted words
__device__ uint32_t g_wbh[1536 * 256];             // QKV B fp16x2 [n][word]
__device__ uint32_t g_wph[512 * 256];              // wp fp16x2 [n][word]
__device__ uint32_t g_vt [(size_t)32 * 64 * 512];  // bf16x2 V^T [z][e][cp], cp-pair-permuted
__device__ uint32_t g_mb [1024 * 32];              // M bit-packed

// ---------------- helpers ----------------
__device__ __forceinline__ uint32_t pack_bf16(float lo, float hi) {
    uint32_t r;
    asm("cvt.rn.bf16x2.f32 %0, %1, %2;" : "=r"(r) : "f"(hi), "f"(lo));
    return r;
}
__device__ __forceinline__ uint32_t pack_f16(float lo, float hi) {
    uint32_t r;
    asm("cvt.rn.f16x2.f32 %0, %1, %2;" : "=r"(r) : "f"(hi), "f"(lo));
    return r;
}
__device__ __forceinline__ uint32_t smem_u32(const void* p) {
    uint32_t a;
    asm("{ .reg .u64 t; cvta.to.shared.u64 t, %1; cvt.u32.u64 %0, t; }" : "=r"(a) : "l"(p));
    return a;
}
__device__ __forceinline__ void cp16(uint32_t dst, const void* src) {
    asm volatile("cp.async.cg.shared.global [%0], [%1], 16;" :: "r"(dst), "l"(src));
}
__device__ __forceinline__ void cp_commit() { asm volatile("cp.async.commit_group;"); }

__device__ __forceinline__ void mma_f16(float d[4], const uint32_t a[4], uint32_t b0, uint32_t b1) {
    asm volatile(
        "mma.sync.aligned.m16n8k16.row.col.f32.f16.f16.f32 "
        "{%0,%1,%2,%3}, {%4,%5,%6,%7}, {%8,%9}, {%0,%1,%2,%3};"
        : "+f"(d[0]), "+f"(d[1]), "+f"(d[2]), "+f"(d[3])
        : "r"(a[0]), "r"(a[1]), "r"(a[2]), "r"(a[3]), "r"(b0), "r"(b1));
}
__device__ __forceinline__ void mma_bf16(float d[4], const uint32_t a[4], uint32_t b0, uint32_t b1) {
    asm volatile(
        "mma.sync.aligned.m16n8k16.row.col.f32.bf16.bf16.f32 "
        "{%0,%1,%2,%3}, {%4,%5,%6,%7}, {%8,%9}, {%0,%1,%2,%3};"
        : "+f"(d[0]), "+f"(d[1]), "+f"(d[2]), "+f"(d[3])
        : "r"(a[0]), "r"(a[1]), "r"(a[2]), "r"(a[3]), "r"(b0), "r"(b1));
}

// ---------------- LayerNorm -> fp16x2 pair-permuted words ----------------
__global__ void ln_kernel(const float* __restrict__ x,
                          const float* __restrict__ gamma,
                          const float* __restrict__ beta) {
    int row = blockIdx.x;
    int t = threadIdx.x;
    float2 v = ((const float2*)(x + (size_t)row * DM))[t];

    __shared__ float red[8];
    float s = v.x + v.y;
    #pragma unroll
    for (int o = 16; o; o >>= 1) s += __shfl_xor_sync(0xffffffffu, s, o);
    if ((t & 31) == 0) red[t >> 5] = s;
    __syncthreads();
    if (t < 8) {
        float m = red[t];
        #pragma unroll
        for (int o = 4; o; o >>= 1) m += __shfl_xor_sync(0xffu, m, o);
        if (t == 0) red[0] = m;
    }
    __syncthreads();
    float mu = red[0] * (1.0f / DM);
    __syncthreads();

    float d0 = v.x - mu, d1 = v.y - mu;
    float s2 = d0 * d0 + d1 * d1;
    #pragma unroll
    for (int o = 16; o; o >>= 1) s2 += __shfl_xor_sync(0xffffffffu, s2, o);
    if ((t & 31) == 0) red[t >> 5] = s2;
    __syncthreads();
    if (t < 8) {
        float m = red[t];
        #pragma unroll
        for (int o = 4; o; o >>= 1) m += __shfl_xor_sync(0xffu, m, o);
        if (t == 0) red[0] = m;
    }
    __syncthreads();
    float rstd = rsqrtf(red[0] * (1.0f / DM) + LNEPS);

    float2 gm = ((const float2*)gamma)[t];
    float2 bt = ((const float2*)beta)[t];
    float n0 = d0 * rstd * gm.x + bt.x;
    float n1 = d1 * rstd * gm.y + bt.y;
    int wp = (t & ~7) | perm3(t & 7);
    g_xnh[(size_t)row * 256 + wp] = pack_f16(n0, n1);
}

// ---------------- prep: weights -> fp16x2 pair-permuted; mask bitpack (merged) ----------------
__global__ void prep_all(const float* __restrict__ wq, const float* __restrict__ wk,
                         const float* __restrict__ wv, const float* __restrict__ wp,
                         const int* __restrict__ M) {
    int bid = blockIdx.x;
    if (bid < 2048) {
        size_t idx = (size_t)bid * 256 + threadIdx.x;
        if (idx < (size_t)1536 * 256) {
            int n = (int)(idx >> 8), u = (int)(idx & 255);
            int sel = n >> 9;
            int he = n & 511;
            int h = he >> 6, e = he & 63;
            const float* w = sel == 0 ? wq : sel == 1 ? wk : wv;
            float v0 = w[((size_t)h * 512 + 2 * u) * 64 + e];
            float v1 = w[((size_t)h * 512 + 2 * u + 1) * 64 + e];
            int wpp = (u & ~7) | perm3(u & 7);
            g_wbh[(size_t)n * 256 + wpp] = pack_f16(v0, v1);
        } else {
            size_t i2 = idx - (size_t)1536 * 256;
            int n = (int)(i2 >> 8), u = (int)(i2 & 255);
            float v0 = wp[(size_t)n * 512 + 2 * u];
            float v1 = wp[(size_t)n * 512 + 2 * u + 1];
            int wpp = (u & ~7) | perm3(u & 7);
            g_wph[(size_t)n * 256 + wpp] = pack_f16(v0, v1);
        }
    } else {
        int idx = (bid - 2048) * 256 + threadIdx.x;
        bool m = M[idx] != 0;
        uint32_t w = __ballot_sync(0xffffffffu, m);
        if ((idx & 31) == 0) g_mb[idx >> 5] = w;
    }
}

// ---------------- fp16 MMA GEMM, 2-stage cp.async (round-9 proven form) ----------------
#define PKW 24
template <int NSUB>
__global__ __launch_bounds__(256) void gemm_h(const uint32_t* __restrict__ A,
                                              const uint32_t* __restrict__ Bw,
                                              float* __restrict__ C,
                                              const float* __restrict__ res,
                                              uint32_t* __restrict__ qk,
                                              uint32_t* __restrict__ vt,
                                              int ldc) {
    constexpr int NBLK = NSUB * 32;
    constexpr int GSTG = (128 + NBLK) * PKW;   // uint32 words per stage
    extern __shared__ uint32_t gsmh[];
    int tid = threadIdx.x, lane = tid & 31, warp = tid >> 5;
    int wm = (warp >> 2) * 64;
    int wn = (warp & 3) * NSUB * 8;
    int m0 = blockIdx.x * 128, n0 = blockIdx.y * NBLK;
    int g = lane >> 2, t4 = lane & 3;

    float acc[4][NSUB][4] = {};

    auto fill = [&](int kt, int s) {
        uint32_t ab = smem_u32(gsmh + s * GSTG);
        uint32_t bb = ab + 128 * PKW * 4;
        #pragma unroll
        for (int i = 0; i < 2; i++) {
            int c = tid + i * 256;
            int r = c >> 2, cc = c & 3;
            cp16(ab + (uint32_t)(r * PKW + cc * 4) * 4,
                 A + (size_t)(m0 + r) * 256 + kt * 16 + cc * 4);
        }
        #pragma unroll
        for (int i = 0; i < NSUB / 2; i++) {
            int c = tid + i * 256;
            int r = c >> 2, cc = c & 3;
            cp16(bb + (uint32_t)(r * PKW + cc * 4) * 4,
                 Bw + (size_t)(n0 + r) * 256 + kt * 16 + cc * 4);
        }
        cp_commit();
    };

    fill(0, 0);
    for (int kt = 0; kt < 16; kt++) {
        int st = kt & 1;
        if (kt + 1 < 16) {
            fill(kt + 1, st ^ 1);
            asm volatile("cp.async.wait_group 1;" ::: "memory");
        } else {
            asm volatile("cp.async.wait_group 0;" ::: "memory");
        }
        __syncthreads();
        const uint32_t* As = gsmh + st * GSTG;
        const uint32_t* Bs = As + 128 * PKW;
        #pragma unroll
        for (int kb = 0; kb < 2; kb++) {
            uint32_t a[4][4], b[NSUB][2];
            #pragma unroll
            for (int mt = 0; mt < 4; mt++) {
                int r = wm + mt * 16 + g;
                uint2 f0 = *(const uint2*)(As + r * PKW + kb * 8 + 2 * t4);
                uint2 f1 = *(const uint2*)(As + (r + 8) * PKW + kb * 8 + 2 * t4);
                a[mt][0] = f0.x;
                a[mt][1] = f1.x;
                a[mt][2] = f0.y;
                a[mt][3] = f1.y;
            }
            #pragma unroll
            for (int nt = 0; nt < NSUB; nt++) {
                int n = wn + nt * 8 + g;
                uint2 bv = *(const uint2*)(Bs + n * PKW + kb * 8 + 2 * t4);
                b[nt][0] = bv.x;
                b[nt][1] = bv.y;
            }
            #pragma unroll
            for (int mt = 0; mt < 4; mt++)
                #pragma unroll
                for (int nt = 0; nt < NSUB; nt++)
                    mma_f16(acc[mt][nt], a[mt], b[nt][0], b[nt][1]);
        }
        __syncthreads();
    }

    if (qk) {
        if (n0 >= 1024) {
            // ---- V: pack bf16 token-pairs transposed into g_vt (cp-pair perm) ----
            bool geven = (g & 1) == 0;
            #pragma unroll
            for (int mt = 0; mt < 4; mt++) {
                int ra = m0 + wm + mt * 16 + g;
                int b_ = ra >> 10, c_ = ra & 1023;
                #pragma unroll
                for (int nt = 0; nt < NSUB; nt++) {
                    int np = n0 - 1024 + wn + nt * 8 + t4 * 2;
                    int h_ = np >> 6, e0 = np & 63;
                    int z_ = h_ * 4 + b_;
                    float v0 = acc[mt][nt][0], v1 = acc[mt][nt][1];
                    float v2 = acc[mt][nt][2], v3 = acc[mt][nt][3];
                    float e0x = __shfl_xor_sync(0xffffffffu, v0, 4);
                    float e1x = __shfl_xor_sync(0xffffffffu, v1, 4);
                    float e2x = __shfl_xor_sync(0xffffffffu, v2, 4);
                    float e3x = __shfl_xor_sync(0xffffffffu, v3, 4);
                    size_t ebase = ((size_t)z_ * 64 + e0) * 512;
                    if (geven) {
                        int cp = c_ >> 1;
                        int cps = (cp & ~7) | perm3(cp & 7);
                        vt[ebase + cps]       = pack_bf16(v0, e0x);
                        vt[ebase + 512 + cps] = pack_bf16(v1, e1x);
                    } else {
                        int cp = (c_ + 7) >> 1;
                        int cps = (cp & ~7) | perm3(cp & 7);
                        vt[ebase + cps]       = pack_bf16(e2x, v2);
                        vt[ebase + 512 + cps] = pack_bf16(e3x, v3);
                    }
                }
            }
        } else {
            // ---- Q/K: pack fp16 e-pairs (pair-permuted) into g_qk ----
            #pragma unroll
            for (int mt = 0; mt < 4; mt++) {
                int r = m0 + wm + mt * 16 + g;
                #pragma unroll
                for (int nt = 0; nt < NSUB; nt++) {
                    int c = n0 + wn + nt * 8 + t4 * 2;
                    int isK = c >= 512;
                    int cl = c & 511;
                    int h_ = cl >> 6, e = cl & 63;
                    int p = e >> 1;
                    int word = h_ * 64 + isK * 32 + ((p & ~7) | perm3(p & 7));
                    qk[(size_t)r * 512 + word] =
                        pack_f16(acc[mt][nt][0], acc[mt][nt][1]);
                    qk[(size_t)(r + 8) * 512 + word] =
                        pack_f16(acc[mt][nt][2], acc[mt][nt][3]);
                }
            }
        }
        return;
    }

    #pragma unroll
    for (int mt = 0; mt < 4; mt++) {
        #pragma unroll
        for (int nt = 0; nt < NSUB; nt++) {
            int r = m0 + wm + mt * 16 + g;
            int c = n0 + wn + nt * 8 + t4 * 2;
            float v0 = acc[mt][nt][0], v1 = acc[mt][nt][1];
            float v2 = acc[mt][nt][2], v3 = acc[mt][nt][3];
            size_t o0 = (size_t)r * ldc + c;
            size_t o1 = (size_t)(r + 8) * ldc + c;
            if (res) {
                float2 r0 = *(const float2*)(res + o0);
                float2 r1 = *(const float2*)(res + o1);
                v0 += r0.x; v1 += r0.y; v2 += r1.x; v3 += r1.y;
            }
            *(float2*)(C + o0) = make_float2(v0, v1);
            *(float2*)(C + o1) = make_float2(v2, v3);
        }
    }
}

// ---------------- fused flash attention: fp16 QK^T, bf16 PV, smem-staged bias ----------------
#define KW    40                                  // K/V smem row stride in words (≡8 mod 32)
#define BW    72                                  // bias smem row stride in words (≡8 mod 32)
#define KV_W  (64 * KW * 2)                       // K + V words per stage
#define FSTG_W (KV_W + 128 * BW)                  // + bias tile (128 q x 64 c fp32)
#define FSTG_B (FSTG_W * 4)                       // 57344 bytes per stage
__global__ __launch_bounds__(256, 2) void flash_kernel(const float* __restrict__ Bb) {
    extern __shared__ uint32_t smu[];
    int z = blockIdx.z;
    int h = z >> 2, b = z & 3;
    int q0 = blockIdx.x * 128;
    int tid = threadIdx.x, lane = tid & 31, warp = tid >> 5;
    int g = lane >> 2, t4 = lane & 3;

    size_t rowbase = (size_t)b * THW;
    uint32_t smbase = smem_u32(smu);

    uint32_t qa[4][4];
    {
        const uint32_t* Q0 = g_qk + (rowbase + q0 + warp * 16 + g) * 512 + h * 64;
        const uint32_t* Q1 = Q0 + 8 * 512;
        #pragma unroll
        for (int kb = 0; kb < 4; kb++) {
            uint2 f0 = *(const uint2*)(Q0 + kb * 8 + 2 * t4);
            uint2 f1 = *(const uint2*)(Q1 + kb * 8 + 2 * t4);
            qa[kb][0] = f0.x;
            qa[kb][1] = f1.x;
            qa[kb][2] = f0.y;
            qa[kb][3] = f1.y;
        }
    }

    float oacc[8][4] = {};
    float rs0 = 0.f, rs1 = 0.f;
    const float* Bz = Bb + (size_t)z * THW * THW;
    int qr0 = q0 + warp * 16 + g;
    int qr1 = qr0 + 8;
    const uint32_t* mrow0 = g_mb + (size_t)qr0 * 32;
    const uint32_t* mrow1 = g_mb + (size_t)qr1 * 32;

    auto fill = [&](int it, int s) {
        int c0 = it * 64;
        uint32_t kb_ = smbase + s * FSTG_B;
        uint32_t vb_ = kb_ + 64 * KW * 4;
        uint32_t bb_ = kb_ + KV_W * 4;
        #pragma unroll
        for (int i = 0; i < 2; i++) {
            int c = tid + i * 256;
            int r = c >> 3, cc = c & 7;
            cp16(kb_ + (uint32_t)(r * KW + cc * 4) * 4,
                 g_qk + (rowbase + c0 + r) * 512 + h * 64 + 32 + cc * 4);
        }
        #pragma unroll
        for (int i = 0; i < 2; i++) {
            int c = tid + i * 256;
            int e = c >> 3, jj = c & 7;
            cp16(vb_ + (uint32_t)(e * KW + jj * 4) * 4,
                 &g_vt[((size_t)(z * 64) + e) * 512 + (c0 >> 1) + jj * 4]);
        }
        // bias tile: 128 q-rows x 64 cols fp32 = 2048 16B chunks
        #pragma unroll
        for (int i = 0; i < 8; i++) {
            int c = tid + i * 256;
            int r = c >> 4, ch = c & 15;
            cp16(bb_ + (uint32_t)(r * BW + ch * 4) * 4,
                 Bz + (size_t)(q0 + r) * THW + c0 + ch * 4);
        }
        cp_commit();
    };

    fill(0, 0);
    for (int it = 0; it < 16; it++) {
        int st = it & 1;
        int c0 = it * 64;

        uint2 mw0 = *(const uint2*)(mrow0 + (c0 >> 5));
        uint2 mw1 = *(const uint2*)(mrow1 + (c0 >> 5));

        if (it < 15) {
            fill(it + 1, st ^ 1);
            asm volatile("cp.async.wait_group 1;" ::: "memory");
        } else {
            asm volatile("cp.async.wait_group 0;" ::: "memory");
        }
        __syncthreads();
        const uint32_t* Ks = smu + st * FSTG_W;
        const uint32_t* Vst = Ks + 64 * KW;
        const float* Bs = (const float*)(Ks + KV_W);
        const float* brow0 = Bs + (warp * 16 + g) * BW + 2 * t4;
        const float* brow1 = brow0 + 8 * BW;

        #pragma unroll
        for (int j = 0; j < 4; j++) {
            float saccA[4] = {}, saccB[4] = {};
            const uint32_t* krA = Ks + (j * 16 + g) * KW;
            const uint32_t* krB = krA + 8 * KW;
            #pragma unroll
            for (int kb = 0; kb < 4; kb++) {
                uint2 fa = *(const uint2*)(krA + kb * 8 + 2 * t4);
                uint2 fb = *(const uint2*)(krB + kb * 8 + 2 * t4);
                mma_f16(saccA, qa[kb], fa.x, fa.y);
                mma_f16(saccB, qa[kb], fb.x, fb.y);
            }

            float2 bA0 = *(const float2*)(brow0 + j * 16);
            float2 bA1 = *(const float2*)(brow1 + j * 16);
            float2 bB0 = *(const float2*)(brow0 + j * 16 + 8);
            float2 bB1 = *(const float2*)(brow1 + j * 16 + 8);

            uint32_t w0 = (j & 2) ? mw0.y : mw0.x;
            uint32_t w1 = (j & 2) ? mw1.y : mw1.x;
            int sh = (j & 1) * 16 + 2 * t4;
            uint32_t a0m = (w0 >> sh) & 1u,       a1m = (w0 >> (sh + 1)) & 1u;
            uint32_t b0m = (w0 >> (sh + 8)) & 1u, b1m = (w0 >> (sh + 9)) & 1u;
            uint32_t c0m = (w1 >> sh) & 1u,       c1m = (w1 >> (sh + 1)) & 1u;
            uint32_t d0m = (w1 >> (sh + 8)) & 1u, d1m = (w1 >> (sh + 9)) & 1u;

            float pA0 = a0m ? 0.f : __expf(fmaf(saccA[0], 0.125f, bA0.x));
            float pA1 = a1m ? 0.f : __expf(fmaf(saccA[1], 0.125f, bA0.y));
            float pA2 = c0m ? 0.f : __expf(fmaf(saccA[2], 0.125f, bA1.x));
            float pA3 = c1m ? 0.f : __expf(fmaf(saccA[3], 0.125f, bA1.y));
            float pB0 = b0m ? 0.f : __expf(fmaf(saccB[0], 0.125f, bB0.x));
            float pB1 = b1m ? 0.f : __expf(fmaf(saccB[1], 0.125f, bB0.y));
            float pB2 = d0m ? 0.f : __expf(fmaf(saccB[2], 0.125f, bB1.x));
            float pB3 = d1m ? 0.f : __expf(fmaf(saccB[3], 0.125f, bB1.y));
            rs0 += pA0 + pA1 + pB0 + pB1;
            rs1 += pA2 + pA3 + pB2 + pB3;

            uint32_t pa[4];
            pa[0] = pack_bf16(pA0, pA1);
            pa[1] = pack_bf16(pA2, pA3);
            pa[2] = pack_bf16(pB0, pB1);
            pa[3] = pack_bf16(pB2, pB3);

            #pragma unroll
            for (int ne = 0; ne < 8; ne++) {
                uint2 bv = *(const uint2*)(Vst + (ne * 8 + g) * KW + j * 8 + 2 * t4);
                mma_bf16(oacc[ne], pa, bv.x, bv.y);
            }
        }
        __syncthreads();
    }

    rs0 += __shfl_xor_sync(0xffffffffu, rs0, 1);
    rs0 += __shfl_xor_sync(0xffffffffu, rs0, 2);
    rs1 += __shfl_xor_sync(0xffffffffu, rs1, 1);
    rs1 += __shfl_xor_sync(0xffffffffu, rs1, 2);
    float inv0 = 1.0f / rs0, inv1 = 1.0f / rs1;

    // store O as fp16x2 pair-permuted words (A operand of proj GEMM)
    size_t orow0 = (rowbase + qr0) * (size_t)256;
    size_t orow1 = (rowbase + qr1) * (size_t)256;
    #pragma unroll
    for (int nt = 0; nt < 8; nt++) {
        int wi = h * 32 + nt * 4 + t4;
        int wpp = (wi & ~7) | perm3(wi & 7);
        g_oh[orow0 + wpp] = pack_f16(oacc[nt][0] * inv0, oacc[nt][1] * inv0);
        g_oh[orow1 + wpp] = pack_f16(oacc[nt][2] * inv1, oacc[nt][3] * inv1);
    }
}

// ---------------- launch ----------------
extern "C" void kernel_launch(void* const* d_in, const int* in_sizes, int n_in,
                              void* d_out, int out_size) {
    const float* x     = (const float*)d_in[0];
    const float* Bb    = (const float*)d_in[1];
    const int*   Mm    = (const int*)  d_in[2];
    const float* gamma = (const float*)d_in[3];
    const float* beta  = (const float*)d_in[4];
    const float* wq    = (const float*)d_in[5];
    const float* wk    = (const float*)d_in[6];
    const float* wv    = (const float*)d_in[7];
    const float* wp    = (const float*)d_in[8];
    float* out = (float*)d_out;

    void *p_xnh, *p_oh, *p_wbh, *p_wph, *p_vt, *p_qk;
    cudaGetSymbolAddress(&p_xnh, g_xnh);
    cudaGetSymbolAddress(&p_oh,  g_oh);
    cudaGetSymbolAddress(&p_wbh, g_wbh);
    cudaGetSymbolAddress(&p_wph, g_wph);
    cudaGetSymbolAddress(&p_vt,  g_vt);
    cudaGetSymbolAddress(&p_qk,  g_qk);

    const int gemm4_smem = (128 + 128) * PKW * 2 * 4;  // 49152
    const int gemm2_smem = (128 + 64)  * PKW * 2 * 4;  // 36864
    const int flash_smem = FSTG_B * 2;                 // 114688
    cudaFuncSetAttribute(gemm_h<4>,    cudaFuncAttributeMaxDynamicSharedMemorySize, gemm4_smem);
    cudaFuncSetAttribute(gemm_h<2>,    cudaFuncAttributeMaxDynamicSharedMemorySize, gemm2_smem);
    cudaFuncSetAttribute(flash_kernel, cudaFuncAttributeMaxDynamicSharedMemorySize, flash_smem);

    ln_kernel<<<TR, 256>>>(x, gamma, beta);
    prep_all<<<2048 + 4096, 256>>>(wq, wk, wv, wp, Mm);
    gemm_h<4><<<dim3(TR / 128, 1536 / 128), 256, gemm4_smem>>>(
        (const uint32_t*)p_xnh, (const uint32_t*)p_wbh, nullptr, nullptr,
        (uint32_t*)p_qk, (uint32_t*)p_vt, 1536);
    flash_kernel<<<dim3(THW / 128, 1, NH * BS), 256, flash_smem>>>(Bb);
    gemm_h<2><<<dim3(TR / 128, DM / 64), 256, gemm2_smem>>>(
        (const uint32_t*)p_oh, (const uint32_t*)p_wph, out, x,
        nullptr, nullptr, DM);
}

// round 14
// speedup vs baseline: 1.5718x; 1.0335x over previous
#include <cuda_runtime.h>
#include <cstdint>

#define THW 1024
#define DM  512
#define NH  8
#define DH  64
#define BS  4
#define TR  (BS*THW)       // 4096
#define LNEPS 1e-5f

// within-8-group permutation making MMA frag word pairs (t4, t4+4) adjacent
__host__ __device__ __forceinline__ int perm3(int r) { return (r < 4) ? 2 * r : 2 * r - 7; }

// ---------------- scratch ----------------
__device__ uint32_t g_xnh[(size_t)TR * 256];       // LN out fp16x2, pair-permuted words
__device__ uint32_t g_qk [(size_t)TR * 512];       // fp16x2 Q|K: [row][h*64 + (k?32:0) + word]
__device__ uint32_t g_oh [(size_t)TR * 256];       // attn out fp16x2, pair-permuted words
__device__ uint32_t g_wbh[1536 * 256];             // QKV B fp16x2 [n][word]
__device__ uint32_t g_wph[512 * 256];              // wp fp16x2 [n][word]
__device__ uint32_t g_vt [(size_t)32 * 64 * 512];  // bf16x2 V^T [z][e][cp], cp-pair-permuted
__device__ uint32_t g_mb [1024 * 32];              // M bit-packed

// ---------------- helpers ----------------
__device__ __forceinline__ uint32_t pack_bf16(float lo, float hi) {
    uint32_t r;
    asm("cvt.rn.bf16x2.f32 %0, %1, %2;" : "=r"(r) : "f"(hi), "f"(lo));
    return r;
}
__device__ __forceinline__ uint32_t pack_f16(float lo, float hi) {
    uint32_t r;
    asm("cvt.rn.f16x2.f32 %0, %1, %2;" : "=r"(r) : "f"(hi), "f"(lo));
    return r;
}
__device__ __forceinline__ uint32_t smem_u32(const void* p) {
    uint32_t a;
    asm("{ .reg .u64 t; cvta.to.shared.u64 t, %1; cvt.u32.u64 %0, t; }" : "=r"(a) : "l"(p));
    return a;
}
__device__ __forceinline__ void cp16(uint32_t dst, const void* src) {
    asm volatile("cp.async.cg.shared.global [%0], [%1], 16;" :: "r"(dst), "l"(src));
}
__device__ __forceinline__ void cp_commit() { asm volatile("cp.async.commit_group;"); }

__device__ __forceinline__ void mma_f16(float d[4], const uint32_t a[4], uint32_t b0, uint32_t b1) {
    asm volatile(
        "mma.sync.aligned.m16n8k16.row.col.f32.f16.f16.f32 "
        "{%0,%1,%2,%3}, {%4,%5,%6,%7}, {%8,%9}, {%0,%1,%2,%3};"
        : "+f"(d[0]), "+f"(d[1]), "+f"(d[2]), "+f"(d[3])
        : "r"(a[0]), "r"(a[1]), "r"(a[2]), "r"(a[3]), "r"(b0), "r"(b1));
}
__device__ __forceinline__ void mma_bf16(float d[4], const uint32_t a[4], uint32_t b0, uint32_t b1) {
    asm volatile(
        "mma.sync.aligned.m16n8k16.row.col.f32.bf16.bf16.f32 "
        "{%0,%1,%2,%3}, {%4,%5,%6,%7}, {%8,%9}, {%0,%1,%2,%3};"
        : "+f"(d[0]), "+f"(d[1]), "+f"(d[2]), "+f"(d[3])
        : "r"(a[0]), "r"(a[1]), "r"(a[2]), "r"(a[3]), "r"(b0), "r"(b1));
}

// ---------------- merged prep: LN + weight pack + mask bitpack ----------------
__global__ void prep_all(const float* __restrict__ x,
                         const float* __restrict__ gamma,
                         const float* __restrict__ beta,
                         const float* __restrict__ wq, const float* __restrict__ wk,
                         const float* __restrict__ wv, const float* __restrict__ wp,
                         const int* __restrict__ M) {
    int bid = blockIdx.x;
    int t = threadIdx.x;
    if (bid < TR) {
        // ---- LayerNorm row, fp16x2 pair-permuted output ----
        int row = bid;
        float2 v = ((const float2*)(x + (size_t)row * DM))[t];

        __shared__ float red[8];
        float s = v.x + v.y;
        #pragma unroll
        for (int o = 16; o; o >>= 1) s += __shfl_xor_sync(0xffffffffu, s, o);
        if ((t & 31) == 0) red[t >> 5] = s;
        __syncthreads();
        if (t < 8) {
            float m = red[t];
            #pragma unroll
            for (int o = 4; o; o >>= 1) m += __shfl_xor_sync(0xffu, m, o);
            if (t == 0) red[0] = m;
        }
        __syncthreads();
        float mu = red[0] * (1.0f / DM);
        __syncthreads();

        float d0 = v.x - mu, d1 = v.y - mu;
        float s2 = d0 * d0 + d1 * d1;
        #pragma unroll
        for (int o = 16; o; o >>= 1) s2 += __shfl_xor_sync(0xffffffffu, s2, o);
        if ((t & 31) == 0) red[t >> 5] = s2;
        __syncthreads();
        if (t < 8) {
            float m = red[t];
            #pragma unroll
            for (int o = 4; o; o >>= 1) m += __shfl_xor_sync(0xffu, m, o);
            if (t == 0) red[0] = m;
        }
        __syncthreads();
        float rstd = rsqrtf(red[0] * (1.0f / DM) + LNEPS);

        float2 gm = ((const float2*)gamma)[t];
        float2 bt = ((const float2*)beta)[t];
        float n0 = d0 * rstd * gm.x + bt.x;
        float n1 = d1 * rstd * gm.y + bt.y;
        int wpp = (t & ~7) | perm3(t & 7);
        g_xnh[(size_t)row * 256 + wpp] = pack_f16(n0, n1);
    } else if (bid < TR + 2048) {
        size_t idx = (size_t)(bid - TR) * 256 + t;
        if (idx < (size_t)1536 * 256) {
            int n = (int)(idx >> 8), u = (int)(idx & 255);
            int sel = n >> 9;
            int he = n & 511;
            int h = he >> 6, e = he & 63;
            const float* w = sel == 0 ? wq : sel == 1 ? wk : wv;
            float v0 = w[((size_t)h * 512 + 2 * u) * 64 + e];
            float v1 = w[((size_t)h * 512 + 2 * u + 1) * 64 + e];
            int wpp = (u & ~7) | perm3(u & 7);
            g_wbh[(size_t)n * 256 + wpp] = pack_f16(v0, v1);
        } else {
            size_t i2 = idx - (size_t)1536 * 256;
            int n = (int)(i2 >> 8), u = (int)(i2 & 255);
            float v0 = wp[(size_t)n * 512 + 2 * u];
            float v1 = wp[(size_t)n * 512 + 2 * u + 1];
            int wpp = (u & ~7) | perm3(u & 7);
            g_wph[(size_t)n * 256 + wpp] = pack_f16(v0, v1);
        }
    } else {
        int idx = (bid - TR - 2048) * 256 + t;
        bool m = M[idx] != 0;
        uint32_t w = __ballot_sync(0xffffffffu, m);
        if ((idx & 31) == 0) g_mb[idx >> 5] = w;
    }
}

// ---------------- fp16 MMA GEMM, 3-stage cp.async, 1 barrier/iter ----------------
#define PKW 24
template <int NSUB>
__global__ __launch_bounds__(256) void gemm_h(const uint32_t* __restrict__ A,
                                              const uint32_t* __restrict__ Bw,
                                              float* __restrict__ C,
                                              const float* __restrict__ res,
                                              uint32_t* __restrict__ qk,
                                              uint32_t* __restrict__ vt,
                                              int ldc) {
    constexpr int NBLK = NSUB * 32;
    constexpr int GSTG = (128 + NBLK) * PKW;   // uint32 words per stage
    extern __shared__ uint32_t gsmh[];
    int tid = threadIdx.x, lane = tid & 31, warp = tid >> 5;
    int wm = (warp >> 2) * 64;
    int wn = (warp & 3) * NSUB * 8;
    int m0 = blockIdx.x * 128, n0 = blockIdx.y * NBLK;
    int g = lane >> 2, t4 = lane & 3;

    float acc[4][NSUB][4] = {};

    auto fill = [&](int kt, int s) {
        uint32_t ab = smem_u32(gsmh + s * GSTG);
        uint32_t bb = ab + 128 * PKW * 4;
        #pragma unroll
        for (int i = 0; i < 2; i++) {
            int c = tid + i * 256;
            int r = c >> 2, cc = c & 3;
            cp16(ab + (uint32_t)(r * PKW + cc * 4) * 4,
                 A + (size_t)(m0 + r) * 256 + kt * 16 + cc * 4);
        }
        #pragma unroll
        for (int i = 0; i < NSUB / 2; i++) {
            int c = tid + i * 256;
            int r = c >> 2, cc = c & 3;
            cp16(bb + (uint32_t)(r * PKW + cc * 4) * 4,
                 Bw + (size_t)(n0 + r) * 256 + kt * 16 + cc * 4);
        }
        cp_commit();
    };

    fill(0, 0);
    fill(1, 1);
    for (int kt = 0; kt < 16; kt++) {
        int st = kt % 3;
        if (kt < 15) asm volatile("cp.async.wait_group 1;" ::: "memory");
        else         asm volatile("cp.async.wait_group 0;" ::: "memory");
        __syncthreads();
        if (kt + 2 < 16) fill(kt + 2, (kt + 2) % 3);

        const uint32_t* As = gsmh + st * GSTG;
        const uint32_t* Bs = As + 128 * PKW;
        #pragma unroll
        for (int kb = 0; kb < 2; kb++) {
            uint32_t a[4][4], b[NSUB][2];
            #pragma unroll
            for (int mt = 0; mt < 4; mt++) {
                int r = wm + mt * 16 + g;
                uint2 f0 = *(const uint2*)(As + r * PKW + kb * 8 + 2 * t4);
                uint2 f1 = *(const uint2*)(As + (r + 8) * PKW + kb * 8 + 2 * t4);
                a[mt][0] = f0.x;
                a[mt][1] = f1.x;
                a[mt][2] = f0.y;
                a[mt][3] = f1.y;
            }
            #pragma unroll
            for (int nt = 0; nt < NSUB; nt++) {
                int n = wn + nt * 8 + g;
                uint2 bv = *(const uint2*)(Bs + n * PKW + kb * 8 + 2 * t4);
                b[nt][0] = bv.x;
                b[nt][1] = bv.y;
            }
            #pragma unroll
            for (int mt = 0; mt < 4; mt++)
                #pragma unroll
                for (int nt = 0; nt < NSUB; nt++)
                    mma_f16(acc[mt][nt], a[mt], b[nt][0], b[nt][1]);
        }
    }

    if (qk) {
        if (n0 >= 1024) {
            // ---- V: pack bf16 token-pairs transposed into g_vt (cp-pair perm) ----
            bool geven = (g & 1) == 0;
            #pragma unroll
            for (int mt = 0; mt < 4; mt++) {
                int ra = m0 + wm + mt * 16 + g;
                int b_ = ra >> 10, c_ = ra & 1023;
                #pragma unroll
                for (int nt = 0; nt < NSUB; nt++) {
                    int np = n0 - 1024 + wn + nt * 8 + t4 * 2;
                    int h_ = np >> 6, e0 = np & 63;
                    int z_ = h_ * 4 + b_;
                    float v0 = acc[mt][nt][0], v1 = acc[mt][nt][1];
                    float v2 = acc[mt][nt][2], v3 = acc[mt][nt][3];
                    float e0x = __shfl_xor_sync(0xffffffffu, v0, 4);
                    float e1x = __shfl_xor_sync(0xffffffffu, v1, 4);
                    float e2x = __shfl_xor_sync(0xffffffffu, v2, 4);
                    float e3x = __shfl_xor_sync(0xffffffffu, v3, 4);
                    size_t ebase = ((size_t)z_ * 64 + e0) * 512;
                    if (geven) {
                        int cp = c_ >> 1;
                        int cps = (cp & ~7) | perm3(cp & 7);
                        vt[ebase + cps]       = pack_bf16(v0, e0x);
                        vt[ebase + 512 + cps] = pack_bf16(v1, e1x);
                    } else {
                        int cp = (c_ + 7) >> 1;
                        int cps = (cp & ~7) | perm3(cp & 7);
                        vt[ebase + cps]       = pack_bf16(e2x, v2);
                        vt[ebase + 512 + cps] = pack_bf16(e3x, v3);
                    }
                }
            }
        } else {
            // ---- Q/K: pack fp16 e-pairs (pair-permuted) into g_qk ----
            #pragma unroll
            for (int mt = 0; mt < 4; mt++) {
                int r = m0 + wm + mt * 16 + g;
                #pragma unroll
                for (int nt = 0; nt < NSUB; nt++) {
                    int c = n0 + wn + nt * 8 + t4 * 2;
                    int isK = c >= 512;
                    int cl = c & 511;
                    int h_ = cl >> 6, e = cl & 63;
                    int p = e >> 1;
                    int word = h_ * 64 + isK * 32 + ((p & ~7) | perm3(p & 7));
                    qk[(size_t)r * 512 + word] =
                        pack_f16(acc[mt][nt][0], acc[mt][nt][1]);
                    qk[(size_t)(r + 8) * 512 + word] =
                        pack_f16(acc[mt][nt][2], acc[mt][nt][3]);
                }
            }
        }
        return;
    }

    #pragma unroll
    for (int mt = 0; mt < 4; mt++) {
        #pragma unroll
        for (int nt = 0; nt < NSUB; nt++) {
            int r = m0 + wm + mt * 16 + g;
            int c = n0 + wn + nt * 8 + t4 * 2;
            float v0 = acc[mt][nt][0], v1 = acc[mt][nt][1];
            float v2 = acc[mt][nt][2], v3 = acc[mt][nt][3];
            size_t o0 = (size_t)r * ldc + c;
            size_t o1 = (size_t)(r + 8) * ldc + c;
            if (res) {
                float2 r0 = *(const float2*)(res + o0);
                float2 r1 = *(const float2*)(res + o1);
                v0 += r0.x; v1 += r0.y; v2 += r1.x; v3 += r1.y;
            }
            *(float2*)(C + o0) = make_float2(v0, v1);
            *(float2*)(C + o1) = make_float2(v2, v3);
        }
    }
}

// ---------------- fused flash attention: fp16 QK^T, bf16 PV, smem-staged bias ----------------
#define KW    40                                  // K/V smem row stride in words (≡8 mod 32)
#define BW    72                                  // bias smem row stride in words (≡8 mod 32)
#define KV_W  (64 * KW * 2)                       // K + V words per stage
#define FSTG_W (KV_W + 128 * BW)                  // + bias tile (128 q x 64 c fp32)
#define FSTG_B (FSTG_W * 4)                       // 57344 bytes per stage
__global__ __launch_bounds__(256, 2) void flash_kernel(const float* __restrict__ Bb) {
    extern __shared__ uint32_t smu[];
    int z = blockIdx.z;
    int h = z >> 2, b = z & 3;
    int q0 = blockIdx.x * 128;
    int tid = threadIdx.x, lane = tid & 31, warp = tid >> 5;
    int g = lane >> 2, t4 = lane & 3;

    size_t rowbase = (size_t)b * THW;
    uint32_t smbase = smem_u32(smu);

    uint32_t qa[4][4];
    {
        const uint32_t* Q0 = g_qk + (rowbase + q0 + warp * 16 + g) * 512 + h * 64;
        const uint32_t* Q1 = Q0 + 8 * 512;
        #pragma unroll
        for (int kb = 0; kb < 4; kb++) {
            uint2 f0 = *(const uint2*)(Q0 + kb * 8 + 2 * t4);
            uint2 f1 = *(const uint2*)(Q1 + kb * 8 + 2 * t4);
            qa[kb][0] = f0.x;
            qa[kb][1] = f1.x;
            qa[kb][2] = f0.y;
            qa[kb][3] = f1.y;
        }
    }

    float oacc[8][4] = {};
    float rs0 = 0.f, rs1 = 0.f;
    const float* Bz = Bb + (size_t)z * THW * THW;
    int qr0 = q0 + warp * 16 + g;
    int qr1 = qr0 + 8;
    const uint32_t* mrow0 = g_mb + (size_t)qr0 * 32;
    const uint32_t* mrow1 = g_mb + (size_t)qr1 * 32;

    auto fill = [&](int it, int s) {
        int c0 = it * 64;
        uint32_t kb_ = smbase + s * FSTG_B;
        uint32_t vb_ = kb_ + 64 * KW * 4;
        uint32_t bb_ = kb_ + KV_W * 4;
        #pragma unroll
        for (int i = 0; i < 2; i++) {
            int c = tid + i * 256;
            int r = c >> 3, cc = c & 7;
            cp16(kb_ + (uint32_t)(r * KW + cc * 4) * 4,
                 g_qk + (rowbase + c0 + r) * 512 + h * 64 + 32 + cc * 4);
        }
        #pragma unroll
        for (int i = 0; i < 2; i++) {
            int c = tid + i * 256;
            int e = c >> 3, jj = c & 7;
            cp16(vb_ + (uint32_t)(e * KW + jj * 4) * 4,
                 &g_vt[((size_t)(z * 64) + e) * 512 + (c0 >> 1) + jj * 4]);
        }
        #pragma unroll
        for (int i = 0; i < 8; i++) {
            int c = tid + i * 256;
            int r = c >> 4, ch = c & 15;
            cp16(bb_ + (uint32_t)(r * BW + ch * 4) * 4,
                 Bz + (size_t)(q0 + r) * THW + c0 + ch * 4);
        }
        cp_commit();
    };

    fill(0, 0);
    for (int it = 0; it < 16; it++) {
        int st = it & 1;
        int c0 = it * 64;

        uint2 mw0 = *(const uint2*)(mrow0 + (c0 >> 5));
        uint2 mw1 = *(const uint2*)(mrow1 + (c0 >> 5));

        if (it < 15) {
            fill(it + 1, st ^ 1);
            asm volatile("cp.async.wait_group 1;" ::: "memory");
        } else {
            asm volatile("cp.async.wait_group 0;" ::: "memory");
        }
        __syncthreads();
        const uint32_t* Ks = smu + st * FSTG_W;
        const uint32_t* Vst = Ks + 64 * KW;
        const float* Bs = (const float*)(Ks + KV_W);
        const float* brow0 = Bs + (warp * 16 + g) * BW + 2 * t4;
        const float* brow1 = brow0 + 8 * BW;

        #pragma unroll
        for (int j = 0; j < 4; j++) {
            float saccA[4] = {}, saccB[4] = {};
            const uint32_t* krA = Ks + (j * 16 + g) * KW;
            const uint32_t* krB = krA + 8 * KW;
            #pragma unroll
            for (int kb = 0; kb < 4; kb++) {
                uint2 fa = *(const uint2*)(krA + kb * 8 + 2 * t4);
                uint2 fb = *(const uint2*)(krB + kb * 8 + 2 * t4);
                mma_f16(saccA, qa[kb], fa.x, fa.y);
                mma_f16(saccB, qa[kb], fb.x, fb.y);
            }

            float2 bA0 = *(const float2*)(brow0 + j * 16);
            float2 bA1 = *(const float2*)(brow1 + j * 16);
            float2 bB0 = *(const float2*)(brow0 + j * 16 + 8);
            float2 bB1 = *(const float2*)(brow1 + j * 16 + 8);

            uint32_t w0 = (j & 2) ? mw0.y : mw0.x;
            uint32_t w1 = (j & 2) ? mw1.y : mw1.x;
            int sh = (j & 1) * 16 + 2 * t4;
            uint32_t a0m = (w0 >> sh) & 1u,       a1m = (w0 >> (sh + 1)) & 1u;
            uint32_t b0m = (w0 >> (sh + 8)) & 1u, b1m = (w0 >> (sh + 9)) & 1u;
            uint32_t c0m = (w1 >> sh) & 1u,       c1m = (w1 >> (sh + 1)) & 1u;
            uint32_t d0m = (w1 >> (sh + 8)) & 1u, d1m = (w1 >> (sh + 9)) & 1u;

            float pA0 = a0m ? 0.f : __expf(fmaf(saccA[0], 0.125f, bA0.x));
            float pA1 = a1m ? 0.f : __expf(fmaf(saccA[1], 0.125f, bA0.y));
            float pA2 = c0m ? 0.f : __expf(fmaf(saccA[2], 0.125f, bA1.x));
            float pA3 = c1m ? 0.f : __expf(fmaf(saccA[3], 0.125f, bA1.y));
            float pB0 = b0m ? 0.f : __expf(fmaf(saccB[0], 0.125f, bB0.x));
            float pB1 = b1m ? 0.f : __expf(fmaf(saccB[1], 0.125f, bB0.y));
            float pB2 = d0m ? 0.f : __expf(fmaf(saccB[2], 0.125f, bB1.x));
            float pB3 = d1m ? 0.f : __expf(fmaf(saccB[3], 0.125f, bB1.y));
            rs0 += pA0 + pA1 + pB0 + pB1;
            rs1 += pA2 + pA3 + pB2 + pB3;

            uint32_t pa[4];
            pa[0] = pack_bf16(pA0, pA1);
            pa[1] = pack_bf16(pA2, pA3);
            pa[2] = pack_bf16(pB0, pB1);
            pa[3] = pack_bf16(pB2, pB3);

            #pragma unroll
            for (int ne = 0; ne < 8; ne++) {
                uint2 bv = *(const uint2*)(Vst + (ne * 8 + g) * KW + j * 8 + 2 * t4);
                mma_bf16(oacc[ne], pa, bv.x, bv.y);
            }
        }
        __syncthreads();
    }

    rs0 += __shfl_xor_sync(0xffffffffu, rs0, 1);
    rs0 += __shfl_xor_sync(0xffffffffu, rs0, 2);
    rs1 += __shfl_xor_sync(0xffffffffu, rs1, 1);
    rs1 += __shfl_xor_sync(0xffffffffu, rs1, 2);
    float inv0 = 1.0f / rs0, inv1 = 1.0f / rs1;

    // store O as fp16x2 pair-permuted words (A operand of proj GEMM)
    size_t orow0 = (rowbase + qr0) * (size_t)256;
    size_t orow1 = (rowbase + qr1) * (size_t)256;
    #pragma unroll
    for (int nt = 0; nt < 8; nt++) {
        int wi = h * 32 + nt * 4 + t4;
        int wpp = (wi & ~7) | perm3(wi & 7);
        g_oh[orow0 + wpp] = pack_f16(oacc[nt][0] * inv0, oacc[nt][1] * inv0);
        g_oh[orow1 + wpp] = pack_f16(oacc[nt][2] * inv1, oacc[nt][3] * inv1);
    }
}

// ---------------- launch ----------------
extern "C" void kernel_launch(void* const* d_in, const int* in_sizes, int n_in,
                              void* d_out, int out_size) {
    const float* x     = (const float*)d_in[0];
    const float* Bb    = (const float*)d_in[1];
    const int*   Mm    = (const int*)  d_in[2];
    const float* gamma = (const float*)d_in[3];
    const float* beta  = (const float*)d_in[4];
    const float* wq    = (const float*)d_in[5];
    const float* wk    = (const float*)d_in[6];
    const float* wv    = (const float*)d_in[7];
    const float* wp    = (const float*)d_in[8];
    float* out = (float*)d_out;

    void *p_xnh, *p_oh, *p_wbh, *p_wph, *p_vt, *p_qk;
    cudaGetSymbolAddress(&p_xnh, g_xnh);
    cudaGetSymbolAddress(&p_oh,  g_oh);
    cudaGetSymbolAddress(&p_wbh, g_wbh);
    cudaGetSymbolAddress(&p_wph, g_wph);
    cudaGetSymbolAddress(&p_vt,  g_vt);
    cudaGetSymbolAddress(&p_qk,  g_qk);

    const int gemm4_smem = (128 + 128) * PKW * 3 * 4;  // 73728
    const int gemm2_smem = (128 + 64)  * PKW * 3 * 4;  // 55296
    const int flash_smem = FSTG_B * 2;                 // 114688
    cudaFuncSetAttribute(gemm_h<4>,    cudaFuncAttributeMaxDynamicSharedMemorySize, gemm4_smem);
    cudaFuncSetAttribute(gemm_h<2>,    cudaFuncAttributeMaxDynamicSharedMemorySize, gemm2_smem);
    cudaFuncSetAttribute(flash_kernel, cudaFuncAttributeMaxDynamicSharedMemorySize, flash_smem);

    prep_all<<<TR + 2048 + 4096, 256>>>(x, gamma, beta, wq, wk, wv, wp, Mm);
    gemm_h<4><<<dim3(TR / 128, 1536 / 128), 256, gemm4_smem>>>(
        (const uint32_t*)p_xnh, (const uint32_t*)p_wbh, nullptr, nullptr,
        (uint32_t*)p_qk, (uint32_t*)p_vt, 1536);
    flash_kernel<<<dim3(THW / 128, 1, NH * BS), 256, flash_smem>>>(Bb);
    gemm_h<2><<<dim3(TR / 128, DM / 64), 256, gemm2_smem>>>(
        (const uint32_t*)p_oh, (const uint32_t*)p_wph, out, x,
        nullptr, nullptr, DM);
}